// round 14
// baseline (speedup 1.0000x reference)
#include <cuda_runtime.h>
#include <cuda_fp16.h>
#include <cstdint>

#define NMAX 100000
#define EMAX 1600000
#define NG   64
// hidden dim = 128: fp16 row = 32 uint2 (4 halves/lane), fp32 row = 32 float4

typedef unsigned long long ull_t;

// ---------------- scratch (static device globals; no allocation) ----------
__device__ uint2  g_bufH[(size_t)NMAX * 32];   // GEMM output (h*dinv) in fp16
__device__ float4 g_bufB[(size_t)NMAX * 32];   // aggregation output (fp32)
__device__ int    g_deg[NMAX];
__device__ int    g_rowptr[NMAX + 1];
__device__ int    g_pos[NMAX];
__device__ int    g_csr[EMAX];
__device__ float  g_pooled[NG * 128];
__device__ float  g_cnt[NG];
__device__ int    g_bsum[128];
__device__ int    g_is64;   // 1 if index tensors are int64, 0 if int32

// ---------------- packed f32x2 helpers (sm_103a FFMA2) ---------------------
__device__ __forceinline__ ull_t pack2(float v) {
    ull_t r;
    unsigned u = __float_as_uint(v);
    asm("mov.b64 %0, {%1, %1};" : "=l"(r) : "r"(u));
    return r;
}
__device__ __forceinline__ void ffma2(ull_t& d, ull_t a, ull_t b) {
    asm("fma.rn.f32x2 %0, %1, %2, %0;" : "+l"(d) : "l"(a), "l"(b));
}
__device__ __forceinline__ void unpack2(ull_t v, float& lo, float& hi) {
    unsigned a, b;
    asm("mov.b64 {%0, %1}, %2;" : "=r"(a), "=r"(b) : "l"(v));
    lo = __uint_as_float(a);
    hi = __uint_as_float(b);
}

__device__ __forceinline__ int idx_src(const int* ei, int E, int i, int is64) {
    return is64 ? ei[2 * i] : ei[i];
}
__device__ __forceinline__ int idx_dst(const int* ei, int E, int i, int is64) {
    return is64 ? ei[2 * (E + i)] : ei[E + i];
}
__device__ __forceinline__ int idx_at(const int* p, int i, int is64) {
    return is64 ? p[2 * i] : p[i];
}
__device__ __forceinline__ float dinv_of(int node) {
    return rsqrtf((float)(g_deg[node] + 1));
}

// fp16 pack/unpack
__device__ __forceinline__ uint2 pack_h4(float a, float b, float c, float d) {
    __half2 h0 = __floats2half2_rn(a, b);
    __half2 h1 = __floats2half2_rn(c, d);
    uint2 u;
    u.x = *reinterpret_cast<unsigned*>(&h0);
    u.y = *reinterpret_cast<unsigned*>(&h1);
    return u;
}
__device__ __forceinline__ void unpack_h4(uint2 u, float4& f) {
    __half2 h0 = *reinterpret_cast<__half2*>(&u.x);
    __half2 h1 = *reinterpret_cast<__half2*>(&u.y);
    float2 a = __half22float2(h0);
    float2 b = __half22float2(h1);
    f.x = a.x; f.y = a.y; f.z = b.x; f.w = b.y;
}

// ---------------- setup0: zero deg/pooled/cnt + dtype detect ---------------
__global__ void k_setup0(const int* __restrict__ ei, int N) {
    int i = blockIdx.x * blockDim.x + threadIdx.x;
    if (i < N) g_deg[i] = 0;
    if (i < NG * 128) g_pooled[i] = 0.f;
    if (i < NG) g_cnt[i] = 0.f;
    if (blockIdx.x == 0 && threadIdx.x < 32) {
        int lane = threadIdx.x, nz = 0;
        #pragma unroll
        for (int k = lane; k < 128; k += 32)
            nz |= (ei[2 * k + 1] != 0);
        unsigned m = __ballot_sync(0xffffffffu, nz != 0);
        if (lane == 0) g_is64 = (m == 0u) ? 1 : 0;
    }
}

// ---------------- degree histogram over dst --------------------------------
__global__ void k_deg(const int* __restrict__ ei, int E) {
    int i = blockIdx.x * blockDim.x + threadIdx.x;
    int is64 = g_is64;
    if (i < E) atomicAdd(&g_deg[idx_dst(ei, E, i, is64)], 1);
}

// ---------------- block-wise inclusive scan of deg -> rowptr[i+1] ---------
__global__ void k_scan1(int N) {
    __shared__ int sh[1024];
    int i = blockIdx.x * 1024 + threadIdx.x;
    int v = (i < N) ? g_deg[i] : 0;
    sh[threadIdx.x] = v;
    __syncthreads();
    #pragma unroll
    for (int off = 1; off < 1024; off <<= 1) {
        int t = (threadIdx.x >= off) ? sh[threadIdx.x - off] : 0;
        __syncthreads();
        sh[threadIdx.x] += t;
        __syncthreads();
    }
    if (i < N) g_rowptr[i + 1] = sh[threadIdx.x];
    if (threadIdx.x == 1023) g_bsum[blockIdx.x] = sh[1023];
}

// parallel exclusive scan of up to 128 block sums
__global__ void k_scan2(int nb) {
    __shared__ int sh[128];
    int t = threadIdx.x;
    int v = (t < nb) ? g_bsum[t] : 0;
    sh[t] = v;
    __syncthreads();
    #pragma unroll
    for (int off = 1; off < 128; off <<= 1) {
        int u = (t >= off) ? sh[t - off] : 0;
        __syncthreads();
        sh[t] += u;
        __syncthreads();
    }
    if (t < nb) g_bsum[t] = sh[t] - v;   // exclusive prefix
}

// finalize rowptr, init pos cursor, count nodes per graph
__global__ void k_scan3(const int* __restrict__ batch, int N) {
    int i = blockIdx.x * 1024 + threadIdx.x;
    if (i < N) {
        int v = g_rowptr[i + 1] + g_bsum[blockIdx.x];
        g_rowptr[i + 1] = v;
        if (i + 1 < N) g_pos[i + 1] = v;
        atomicAdd(&g_cnt[idx_at(batch, i, g_is64)], 1.0f);
    }
    if (i == 0) { g_rowptr[0] = 0; g_pos[0] = 0; }
}

// ---------------- CSR build: csr[slot(dst)] = src --------------------------
__global__ void k_build(const int* __restrict__ ei, int E) {
    int i = blockIdx.x * blockDim.x + threadIdx.x;
    int is64 = g_is64;
    if (i < E) {
        int d = idx_dst(ei, E, i, is64);
        int p = atomicAdd(&g_pos[d], 1);
        g_csr[p] = idx_src(ei, E, i, is64);
    }
}

// ---------------- GEMM: g_bufH = fp16((IN[N,K] @ W[K,128]) * dinv[row]) ----
// 64x128 tile, 256 threads, K-tile 32, FFMA2 row-pairs (round-9 proven best).
#define XS_STRIDE 66
template <int USE_EXT>
__global__ __launch_bounds__(256) void k_gemm(
    const float4* __restrict__ Xext,
    const float4* __restrict__ W4, int N, int K)
{
    __shared__ float  xs_t[32 * XS_STRIDE];   // transposed X tile [kk][row]
    __shared__ float4 ws4[32 * 32];           // W tile [kk][col4]
    const float4* X = USE_EXT ? Xext : g_bufB;
    const int K4 = K >> 2;

    int tid = threadIdx.x;
    int row0 = blockIdx.x * 64;
    int tx = tid & 31;   // col group: cols [tx*4, tx*4+3]
    int ty = tid >> 5;   // row group: rows [ty*8, ty*8+7] = 4 row-pairs

    ull_t acc[4][4];
    #pragma unroll
    for (int rp = 0; rp < 4; rp++)
        #pragma unroll
        for (int c = 0; c < 4; c++) acc[rp][c] = 0ull;

    for (int k0 = 0; k0 < K; k0 += 32) {
        int k0q = k0 >> 2;
        // load X tile: 64 rows x 8 float4, store transposed [kk][row]
        #pragma unroll
        for (int t = 0; t < 2; t++) {
            int f4 = tid + t * 256;
            int row = f4 >> 3;
            int kk4 = f4 & 7;
            float4 v = make_float4(0.f, 0.f, 0.f, 0.f);
            int gr = row0 + row;
            if (gr < N)
                v = X[(size_t)gr * K4 + k0q + kk4];
            xs_t[(kk4 * 4 + 0) * XS_STRIDE + row] = v.x;
            xs_t[(kk4 * 4 + 1) * XS_STRIDE + row] = v.y;
            xs_t[(kk4 * 4 + 2) * XS_STRIDE + row] = v.z;
            xs_t[(kk4 * 4 + 3) * XS_STRIDE + row] = v.w;
        }
        // load W tile: 32 k-rows x 32 float4
        {
            int kk = tid >> 5;
            int c4 = tid & 31;
            #pragma unroll
            for (int rep = 0; rep < 4; rep++) {
                int kkk = kk + rep * 8;
                ws4[kkk * 32 + c4] = W4[(size_t)(k0 + kkk) * 32 + c4];
            }
        }
        __syncthreads();
        #pragma unroll
        for (int kk = 0; kk < 32; kk++) {
            float4 b = ws4[kk * 32 + tx];
            ull_t bx = pack2(b.x);
            ull_t by = pack2(b.y);
            ull_t bz = pack2(b.z);
            ull_t bw = pack2(b.w);
            const float* ar = xs_t + kk * XS_STRIDE + ty * 8;
            #pragma unroll
            for (int rp = 0; rp < 4; rp++) {
                ull_t a2 = *reinterpret_cast<const ull_t*>(ar + rp * 2);
                ffma2(acc[rp][0], a2, bx);
                ffma2(acc[rp][1], a2, by);
                ffma2(acc[rp][2], a2, bz);
                ffma2(acc[rp][3], a2, bw);
            }
        }
        __syncthreads();
    }
    #pragma unroll
    for (int rp = 0; rp < 4; rp++) {
        int re = row0 + ty * 8 + rp * 2;   // even row
        if (re < N) {
            float x0, x1, y0, y1, z0, z1, w0, w1;
            unpack2(acc[rp][0], x0, x1);
            unpack2(acc[rp][1], y0, y1);
            unpack2(acc[rp][2], z0, z1);
            unpack2(acc[rp][3], w0, w1);
            float d0 = dinv_of(re);
            g_bufH[(size_t)re * 32 + tx] =
                pack_h4(x0 * d0, y0 * d0, z0 * d0, w0 * d0);
            if (re + 1 < N) {
                float d1 = dinv_of(re + 1);
                g_bufH[(size_t)(re + 1) * 32 + tx] =
                    pack_h4(x1 * d1, y1 * d1, z1 * d1, w1 * d1);
            }
        }
    }
}

// ---------------- fp16 gather: full 128-feature row, 1 LDG.64/lane/edge ----
__device__ __forceinline__ float4 gather_sum_h(int w, int lane) {
    float4 acc;
    unpack_h4(g_bufH[(size_t)w * 32 + lane], acc);   // self loop
    int beg = g_rowptr[w], end = g_rowptr[w + 1];
    int j = beg;
    for (; j + 3 < end; j += 4) {
        int s0 = g_csr[j + 0];
        int s1 = g_csr[j + 1];
        int s2 = g_csr[j + 2];
        int s3 = g_csr[j + 3];
        uint2 u0 = g_bufH[(size_t)s0 * 32 + lane];
        uint2 u1 = g_bufH[(size_t)s1 * 32 + lane];
        uint2 u2 = g_bufH[(size_t)s2 * 32 + lane];
        uint2 u3 = g_bufH[(size_t)s3 * 32 + lane];
        float4 v0, v1, v2, v3;
        unpack_h4(u0, v0); unpack_h4(u1, v1);
        unpack_h4(u2, v2); unpack_h4(u3, v3);
        acc.x += (v0.x + v1.x) + (v2.x + v3.x);
        acc.y += (v0.y + v1.y) + (v2.y + v3.y);
        acc.z += (v0.z + v1.z) + (v2.z + v3.z);
        acc.w += (v0.w + v1.w) + (v2.w + v3.w);
    }
    for (; j < end; j++) {
        int s = g_csr[j];
        float4 v;
        unpack_h4(g_bufH[(size_t)s * 32 + lane], v);
        acc.x += v.x; acc.y += v.y; acc.z += v.z; acc.w += v.w;
    }
    return acc;
}

// ---------------- aggregation: warp per node, bufH -> bufB (fp32) ----------
__global__ __launch_bounds__(256) void k_aggr(
    const float* __restrict__ bias, int N, int relu)
{
    int w = (blockIdx.x * blockDim.x + threadIdx.x) >> 5;
    int lane = threadIdx.x & 31;
    if (w >= N) return;
    float4 acc = gather_sum_h(w, lane);
    float di = dinv_of(w);
    float bx = bias[lane * 4 + 0];
    float by = bias[lane * 4 + 1];
    float bz = bias[lane * 4 + 2];
    float bw = bias[lane * 4 + 3];
    float4 o;
    o.x = acc.x * di + bx;
    o.y = acc.y * di + by;
    o.z = acc.z * di + bz;
    o.w = acc.w * di + bw;
    if (relu) {
        o.x = fmaxf(o.x, 0.f); o.y = fmaxf(o.y, 0.f);
        o.z = fmaxf(o.z, 0.f); o.w = fmaxf(o.w, 0.f);
    }
    g_bufB[(size_t)w * 32 + lane] = o;
}

// ---------------- layer-3 aggregation fused with pooling ------------------
__global__ __launch_bounds__(256) void k_aggr_pool(
    const float* __restrict__ bias,
    const int* __restrict__ batch, int N)
{
    int w = (blockIdx.x * blockDim.x + threadIdx.x) >> 5;
    int lane = threadIdx.x & 31;
    if (w >= N) return;
    float4 acc = gather_sum_h(w, lane);
    float di = dinv_of(w);
    float bx = bias[lane * 4 + 0];
    float by = bias[lane * 4 + 1];
    float bz = bias[lane * 4 + 2];
    float bw = bias[lane * 4 + 3];
    int g = idx_at(batch, w, g_is64);
    float* p = g_pooled + g * 128 + lane * 4;
    atomicAdd(p + 0, acc.x * di + bx);
    atomicAdd(p + 1, acc.y * di + by);
    atomicAdd(p + 2, acc.z * di + bz);
    atomicAdd(p + 3, acc.w * di + bw);
}

// ---------------- head: out[g,c] = (pooled[g]/cnt[g]) @ Wc + bc -----------
__global__ void k_final(const float* __restrict__ Wc,
                        const float* __restrict__ bc,
                        float* __restrict__ out)
{
    int t = threadIdx.x;   // 128 threads: (g, c)
    if (t >= NG * 2) return;
    int g = t >> 1;
    int c = t & 1;
    float s = 0.f;
    const float* p = g_pooled + g * 128;
    #pragma unroll 8
    for (int f = 0; f < 128; f++) s += p[f] * Wc[f * 2 + c];
    float inv = 1.f / fmaxf(g_cnt[g], 1.0f);
    out[t] = s * inv + bc[c];
}

// ---------------- launch ----------------------------------------------------
extern "C" void kernel_launch(void* const* d_in, const int* in_sizes, int n_in,
                              void* d_out, int out_size) {
    const float* x     = (const float*)d_in[0];
    const int*   ei    = (const int*)d_in[1];     // int32 (or int64, auto-detected)
    const int*   batch = (const int*)d_in[2];
    const float* W1 = (const float*)d_in[3];
    const float* b1 = (const float*)d_in[4];
    const float* W2 = (const float*)d_in[5];
    const float* b2 = (const float*)d_in[6];
    const float* W3 = (const float*)d_in[7];
    const float* b3 = (const float*)d_in[8];
    const float* Wc = (const float*)d_in[9];
    const float* bc = (const float*)d_in[10];
    float* out = (float*)d_out;

    const int Fin = 256;
    int N = in_sizes[0] / Fin;
    int E = in_sizes[1] / 2;

    int nb1024 = (N + 1023) / 1024;
    int gN256  = (N + 255) / 256;
    int gE256  = (E + 255) / 256;
    int gWarp  = (int)(((long long)N * 32 + 255) / 256);
    int gGemm  = (N + 63) / 64;

    // launches 1-3
    k_setup0<<<gN256, 256>>>(ei, N);                                   // 1
    k_deg<<<gE256, 256>>>(ei, E);                                      // 2
    k_scan1<<<nb1024, 1024>>>(N);                                      // 3

    // launch 4: layer-1 GEMM (profiled by ncu) — needs only g_deg
    k_gemm<1><<<gGemm, 256>>>((const float4*)x, (const float4*)W1, N, 256);  // 4

    // finish CSR
    k_scan2<<<1, 128>>>(nb1024);                                       // 5
    k_scan3<<<nb1024, 1024>>>(batch, N);                               // 6
    k_build<<<gE256, 256>>>(ei, E);                                    // 7

    // layer 1 aggregate -> bufB
    // MEASUREMENT: k_aggr is idempotent (reads bufH/rowptr/csr, writes bufB).
    // 5 total invocations; timed delta vs round-13 baseline = 4x one pass.
    k_aggr<<<gWarp, 256>>>(b1, N, 1);                                  // 8
    k_aggr<<<gWarp, 256>>>(b1, N, 1);                                  // 9  (dup)
    k_aggr<<<gWarp, 256>>>(b1, N, 1);                                  // 10 (dup)
    k_aggr<<<gWarp, 256>>>(b1, N, 1);                                  // 11 (dup)
    k_aggr<<<gWarp, 256>>>(b1, N, 1);                                  // 12 (dup)

    // layer 2
    k_gemm<0><<<gGemm, 256>>>((const float4*)x, (const float4*)W2, N, 128);  // 13
    k_aggr<<<gWarp, 256>>>(b2, N, 1);                                  // 14

    // layer 3 + pool
    k_gemm<0><<<gGemm, 256>>>((const float4*)x, (const float4*)W3, N, 128);  // 15
    k_aggr_pool<<<gWarp, 256>>>(b3, batch, N);                         // 16

    // head
    k_final<<<1, 128>>>(Wc, bc, out);                                  // 17
}

// round 15
// speedup vs baseline: 1.8857x; 1.8857x over previous
#include <cuda_runtime.h>
#include <cuda_fp16.h>
#include <cstdint>

#define NMAX 100000
#define EMAX 1600000
#define NG   64
// hidden dim = 128: fp16 row = 32 uint2 (4 halves/lane), fp32 row = 32 float4

typedef unsigned long long ull_t;

// ---------------- scratch (static device globals; no allocation) ----------
__device__ uint2  g_bufH[(size_t)NMAX * 32];   // GEMM output (h*dinv) in fp16
__device__ float4 g_bufB[(size_t)NMAX * 32];   // aggregation output (fp32)
__device__ int    g_deg[NMAX];
__device__ int    g_rowptr[NMAX + 1];
__device__ int    g_pos[NMAX];
__device__ int    g_csr[EMAX];
__device__ float  g_pooled[NG * 128];
__device__ float  g_cnt[NG];
__device__ int    g_bsum[128];
__device__ int    g_is64;   // 1 if index tensors are int64, 0 if int32

// ---------------- packed f32x2 helpers (sm_103a FFMA2) ---------------------
__device__ __forceinline__ ull_t pack2(float v) {
    ull_t r;
    unsigned u = __float_as_uint(v);
    asm("mov.b64 %0, {%1, %1};" : "=l"(r) : "r"(u));
    return r;
}
__device__ __forceinline__ void ffma2(ull_t& d, ull_t a, ull_t b) {
    asm("fma.rn.f32x2 %0, %1, %2, %0;" : "+l"(d) : "l"(a), "l"(b));
}
__device__ __forceinline__ void unpack2(ull_t v, float& lo, float& hi) {
    unsigned a, b;
    asm("mov.b64 {%0, %1}, %2;" : "=r"(a), "=r"(b) : "l"(v));
    lo = __uint_as_float(a);
    hi = __uint_as_float(b);
}

__device__ __forceinline__ int idx_src(const int* ei, int E, int i, int is64) {
    return is64 ? ei[2 * i] : ei[i];
}
__device__ __forceinline__ int idx_dst(const int* ei, int E, int i, int is64) {
    return is64 ? ei[2 * (E + i)] : ei[E + i];
}
__device__ __forceinline__ int idx_at(const int* p, int i, int is64) {
    return is64 ? p[2 * i] : p[i];
}
__device__ __forceinline__ float dinv_of(int node) {
    return rsqrtf((float)(g_deg[node] + 1));
}

// fp16 pack/unpack
__device__ __forceinline__ uint2 pack_h4(float a, float b, float c, float d) {
    __half2 h0 = __floats2half2_rn(a, b);
    __half2 h1 = __floats2half2_rn(c, d);
    uint2 u;
    u.x = *reinterpret_cast<unsigned*>(&h0);
    u.y = *reinterpret_cast<unsigned*>(&h1);
    return u;
}
__device__ __forceinline__ void unpack_h4(uint2 u, float4& f) {
    __half2 h0 = *reinterpret_cast<__half2*>(&u.x);
    __half2 h1 = *reinterpret_cast<__half2*>(&u.y);
    float2 a = __half22float2(h0);
    float2 b = __half22float2(h1);
    f.x = a.x; f.y = a.y; f.z = b.x; f.w = b.y;
}

// ---------------- setup0: zero deg/pooled/cnt + dtype detect ---------------
__global__ void k_setup0(const int* __restrict__ ei, int N) {
    int i = blockIdx.x * blockDim.x + threadIdx.x;
    if (i < N) g_deg[i] = 0;
    if (i < NG * 128) g_pooled[i] = 0.f;
    if (i < NG) g_cnt[i] = 0.f;
    if (blockIdx.x == 0 && threadIdx.x < 32) {
        int lane = threadIdx.x, nz = 0;
        #pragma unroll
        for (int k = lane; k < 128; k += 32)
            nz |= (ei[2 * k + 1] != 0);
        unsigned m = __ballot_sync(0xffffffffu, nz != 0);
        if (lane == 0) g_is64 = (m == 0u) ? 1 : 0;
    }
}

// ---------------- degree histogram over dst --------------------------------
__global__ void k_deg(const int* __restrict__ ei, int E) {
    int i = blockIdx.x * blockDim.x + threadIdx.x;
    int is64 = g_is64;
    if (i < E) atomicAdd(&g_deg[idx_dst(ei, E, i, is64)], 1);
}

// ---------------- block-wise inclusive scan of deg -> rowptr[i+1] ---------
__global__ void k_scan1(int N) {
    __shared__ int sh[1024];
    int i = blockIdx.x * 1024 + threadIdx.x;
    int v = (i < N) ? g_deg[i] : 0;
    sh[threadIdx.x] = v;
    __syncthreads();
    #pragma unroll
    for (int off = 1; off < 1024; off <<= 1) {
        int t = (threadIdx.x >= off) ? sh[threadIdx.x - off] : 0;
        __syncthreads();
        sh[threadIdx.x] += t;
        __syncthreads();
    }
    if (i < N) g_rowptr[i + 1] = sh[threadIdx.x];
    if (threadIdx.x == 1023) g_bsum[blockIdx.x] = sh[1023];
}

// parallel exclusive scan of up to 128 block sums
__global__ void k_scan2(int nb) {
    __shared__ int sh[128];
    int t = threadIdx.x;
    int v = (t < nb) ? g_bsum[t] : 0;
    sh[t] = v;
    __syncthreads();
    #pragma unroll
    for (int off = 1; off < 128; off <<= 1) {
        int u = (t >= off) ? sh[t - off] : 0;
        __syncthreads();
        sh[t] += u;
        __syncthreads();
    }
    if (t < nb) g_bsum[t] = sh[t] - v;   // exclusive prefix
}

// finalize rowptr, init pos cursor, count nodes per graph
__global__ void k_scan3(const int* __restrict__ batch, int N) {
    int i = blockIdx.x * 1024 + threadIdx.x;
    if (i < N) {
        int v = g_rowptr[i + 1] + g_bsum[blockIdx.x];
        g_rowptr[i + 1] = v;
        if (i + 1 < N) g_pos[i + 1] = v;
        atomicAdd(&g_cnt[idx_at(batch, i, g_is64)], 1.0f);
    }
    if (i == 0) { g_rowptr[0] = 0; g_pos[0] = 0; }
}

// ---------------- CSR build: csr[slot(dst)] = src --------------------------
__global__ void k_build(const int* __restrict__ ei, int E) {
    int i = blockIdx.x * blockDim.x + threadIdx.x;
    int is64 = g_is64;
    if (i < E) {
        int d = idx_dst(ei, E, i, is64);
        int p = atomicAdd(&g_pos[d], 1);
        g_csr[p] = idx_src(ei, E, i, is64);
    }
}

// ---------------- GEMM: g_bufH = fp16((IN[N,K] @ W[K,128]) * dinv[row]) ----
// 64x128 tile, 256 threads, K-tile 32, FFMA2 row-pairs (round-9 proven best).
#define XS_STRIDE 66
template <int USE_EXT>
__global__ __launch_bounds__(256) void k_gemm(
    const float4* __restrict__ Xext,
    const float4* __restrict__ W4, int N, int K)
{
    __shared__ float  xs_t[32 * XS_STRIDE];   // transposed X tile [kk][row]
    __shared__ float4 ws4[32 * 32];           // W tile [kk][col4]
    const float4* X = USE_EXT ? Xext : g_bufB;
    const int K4 = K >> 2;

    int tid = threadIdx.x;
    int row0 = blockIdx.x * 64;
    int tx = tid & 31;   // col group: cols [tx*4, tx*4+3]
    int ty = tid >> 5;   // row group: rows [ty*8, ty*8+7] = 4 row-pairs

    ull_t acc[4][4];
    #pragma unroll
    for (int rp = 0; rp < 4; rp++)
        #pragma unroll
        for (int c = 0; c < 4; c++) acc[rp][c] = 0ull;

    for (int k0 = 0; k0 < K; k0 += 32) {
        int k0q = k0 >> 2;
        // load X tile: 64 rows x 8 float4, store transposed [kk][row]
        #pragma unroll
        for (int t = 0; t < 2; t++) {
            int f4 = tid + t * 256;
            int row = f4 >> 3;
            int kk4 = f4 & 7;
            float4 v = make_float4(0.f, 0.f, 0.f, 0.f);
            int gr = row0 + row;
            if (gr < N)
                v = X[(size_t)gr * K4 + k0q + kk4];
            xs_t[(kk4 * 4 + 0) * XS_STRIDE + row] = v.x;
            xs_t[(kk4 * 4 + 1) * XS_STRIDE + row] = v.y;
            xs_t[(kk4 * 4 + 2) * XS_STRIDE + row] = v.z;
            xs_t[(kk4 * 4 + 3) * XS_STRIDE + row] = v.w;
        }
        // load W tile: 32 k-rows x 32 float4
        {
            int kk = tid >> 5;
            int c4 = tid & 31;
            #pragma unroll
            for (int rep = 0; rep < 4; rep++) {
                int kkk = kk + rep * 8;
                ws4[kkk * 32 + c4] = W4[(size_t)(k0 + kkk) * 32 + c4];
            }
        }
        __syncthreads();
        #pragma unroll
        for (int kk = 0; kk < 32; kk++) {
            float4 b = ws4[kk * 32 + tx];
            ull_t bx = pack2(b.x);
            ull_t by = pack2(b.y);
            ull_t bz = pack2(b.z);
            ull_t bw = pack2(b.w);
            const float* ar = xs_t + kk * XS_STRIDE + ty * 8;
            #pragma unroll
            for (int rp = 0; rp < 4; rp++) {
                ull_t a2 = *reinterpret_cast<const ull_t*>(ar + rp * 2);
                ffma2(acc[rp][0], a2, bx);
                ffma2(acc[rp][1], a2, by);
                ffma2(acc[rp][2], a2, bz);
                ffma2(acc[rp][3], a2, bw);
            }
        }
        __syncthreads();
    }
    #pragma unroll
    for (int rp = 0; rp < 4; rp++) {
        int re = row0 + ty * 8 + rp * 2;   // even row
        if (re < N) {
            float x0, x1, y0, y1, z0, z1, w0, w1;
            unpack2(acc[rp][0], x0, x1);
            unpack2(acc[rp][1], y0, y1);
            unpack2(acc[rp][2], z0, z1);
            unpack2(acc[rp][3], w0, w1);
            float d0 = dinv_of(re);
            g_bufH[(size_t)re * 32 + tx] =
                pack_h4(x0 * d0, y0 * d0, z0 * d0, w0 * d0);
            if (re + 1 < N) {
                float d1 = dinv_of(re + 1);
                g_bufH[(size_t)(re + 1) * 32 + tx] =
                    pack_h4(x1 * d1, y1 * d1, z1 * d1, w1 * d1);
            }
        }
    }
}

// ---------------- fp16 gather: full 128-feature row, 1 LDG.64/lane/edge ----
__device__ __forceinline__ float4 gather_sum_h(int w, int lane) {
    float4 acc;
    unpack_h4(g_bufH[(size_t)w * 32 + lane], acc);   // self loop
    int beg = g_rowptr[w], end = g_rowptr[w + 1];
    int j = beg;
    for (; j + 3 < end; j += 4) {
        int s0 = g_csr[j + 0];
        int s1 = g_csr[j + 1];
        int s2 = g_csr[j + 2];
        int s3 = g_csr[j + 3];
        uint2 u0 = g_bufH[(size_t)s0 * 32 + lane];
        uint2 u1 = g_bufH[(size_t)s1 * 32 + lane];
        uint2 u2 = g_bufH[(size_t)s2 * 32 + lane];
        uint2 u3 = g_bufH[(size_t)s3 * 32 + lane];
        float4 v0, v1, v2, v3;
        unpack_h4(u0, v0); unpack_h4(u1, v1);
        unpack_h4(u2, v2); unpack_h4(u3, v3);
        acc.x += (v0.x + v1.x) + (v2.x + v3.x);
        acc.y += (v0.y + v1.y) + (v2.y + v3.y);
        acc.z += (v0.z + v1.z) + (v2.z + v3.z);
        acc.w += (v0.w + v1.w) + (v2.w + v3.w);
    }
    for (; j < end; j++) {
        int s = g_csr[j];
        float4 v;
        unpack_h4(g_bufH[(size_t)s * 32 + lane], v);
        acc.x += v.x; acc.y += v.y; acc.z += v.z; acc.w += v.w;
    }
    return acc;
}

// ---------------- aggregation: warp per node, bufH -> bufB (fp32) ----------
__global__ __launch_bounds__(256) void k_aggr(
    const float* __restrict__ bias, int N, int relu)
{
    int w = (blockIdx.x * blockDim.x + threadIdx.x) >> 5;
    int lane = threadIdx.x & 31;
    if (w >= N) return;
    float4 acc = gather_sum_h(w, lane);
    float di = dinv_of(w);
    float bx = bias[lane * 4 + 0];
    float by = bias[lane * 4 + 1];
    float bz = bias[lane * 4 + 2];
    float bw = bias[lane * 4 + 3];
    float4 o;
    o.x = acc.x * di + bx;
    o.y = acc.y * di + by;
    o.z = acc.z * di + bz;
    o.w = acc.w * di + bw;
    if (relu) {
        o.x = fmaxf(o.x, 0.f); o.y = fmaxf(o.y, 0.f);
        o.z = fmaxf(o.z, 0.f); o.w = fmaxf(o.w, 0.f);
    }
    g_bufB[(size_t)w * 32 + lane] = o;
}

// ---------------- layer-3 aggregation + pooling with block pre-reduction ---
// batch is sorted, so a block's 8 nodes almost always share one graph.
// Uniform blocks reduce in shared and issue ONE atomic set (8x fewer global
// atomics to the tiny g_pooled array = the contention hot spot).
__global__ __launch_bounds__(256) void k_aggr_pool(
    const float* __restrict__ bias,
    const int* __restrict__ batch, int N)
{
    __shared__ float sacc[8 * 128];
    __shared__ int   sg[8];
    int wid = threadIdx.x >> 5;
    int lane = threadIdx.x & 31;
    int w = blockIdx.x * 8 + wid;
    bool valid = (w < N);

    float4 o = make_float4(0.f, 0.f, 0.f, 0.f);
    int g = -1;
    if (valid) {
        float4 acc = gather_sum_h(w, lane);
        float di = dinv_of(w);
        o.x = acc.x * di + bias[lane * 4 + 0];
        o.y = acc.y * di + bias[lane * 4 + 1];
        o.z = acc.z * di + bias[lane * 4 + 2];
        o.w = acc.w * di + bias[lane * 4 + 3];
        g = idx_at(batch, w, g_is64);
    }
    if (lane == 0) sg[wid] = g;
    float* row = sacc + wid * 128 + lane * 4;
    row[0] = o.x; row[1] = o.y; row[2] = o.z; row[3] = o.w;
    __syncthreads();

    int g0 = sg[0];
    bool uniform = (g0 >= 0);
    #pragma unroll
    for (int i = 1; i < 8; i++) {
        int gi = sg[i];
        if (gi >= 0 && gi != g0) uniform = false;
    }

    if (uniform) {
        if (wid == 0) {
            #pragma unroll
            for (int c = 0; c < 4; c++) {
                int f = lane * 4 + c;
                float s = 0.f;
                #pragma unroll
                for (int r = 0; r < 8; r++) s += sacc[r * 128 + f];
                atomicAdd(&g_pooled[g0 * 128 + f], s);
            }
        }
    } else if (valid) {
        float* p = g_pooled + g * 128 + lane * 4;
        atomicAdd(p + 0, o.x);
        atomicAdd(p + 1, o.y);
        atomicAdd(p + 2, o.z);
        atomicAdd(p + 3, o.w);
    }
}

// ---------------- head: out[g,c] = (pooled[g]/cnt[g]) @ Wc + bc -----------
__global__ void k_final(const float* __restrict__ Wc,
                        const float* __restrict__ bc,
                        float* __restrict__ out)
{
    int t = threadIdx.x;   // 128 threads: (g, c)
    if (t >= NG * 2) return;
    int g = t >> 1;
    int c = t & 1;
    float s = 0.f;
    const float* p = g_pooled + g * 128;
    #pragma unroll 8
    for (int f = 0; f < 128; f++) s += p[f] * Wc[f * 2 + c];
    float inv = 1.f / fmaxf(g_cnt[g], 1.0f);
    out[t] = s * inv + bc[c];
}

// ---------------- launch ----------------------------------------------------
extern "C" void kernel_launch(void* const* d_in, const int* in_sizes, int n_in,
                              void* d_out, int out_size) {
    const float* x     = (const float*)d_in[0];
    const int*   ei    = (const int*)d_in[1];     // int32 (or int64, auto-detected)
    const int*   batch = (const int*)d_in[2];
    const float* W1 = (const float*)d_in[3];
    const float* b1 = (const float*)d_in[4];
    const float* W2 = (const float*)d_in[5];
    const float* b2 = (const float*)d_in[6];
    const float* W3 = (const float*)d_in[7];
    const float* b3 = (const float*)d_in[8];
    const float* Wc = (const float*)d_in[9];
    const float* bc = (const float*)d_in[10];
    float* out = (float*)d_out;

    const int Fin = 256;
    int N = in_sizes[0] / Fin;
    int E = in_sizes[1] / 2;

    int nb1024 = (N + 1023) / 1024;
    int gN256  = (N + 255) / 256;
    int gE256  = (E + 255) / 256;
    int gWarp  = (int)(((long long)N * 32 + 255) / 256);
    int gGemm  = (N + 63) / 64;

    // launches 1-3
    k_setup0<<<gN256, 256>>>(ei, N);                                   // 1
    k_deg<<<gE256, 256>>>(ei, E);                                      // 2
    k_scan1<<<nb1024, 1024>>>(N);                                      // 3

    // launch 4: layer-1 GEMM (profiled by ncu) — needs only g_deg
    k_gemm<1><<<gGemm, 256>>>((const float4*)x, (const float4*)W1, N, 256);  // 4

    // finish CSR
    k_scan2<<<1, 128>>>(nb1024);                                       // 5
    k_scan3<<<nb1024, 1024>>>(batch, N);                               // 6
    k_build<<<gE256, 256>>>(ei, E);                                    // 7

    // layer 1 aggregate -> bufB
    k_aggr<<<gWarp, 256>>>(b1, N, 1);                                  // 8

    // layer 2
    k_gemm<0><<<gGemm, 256>>>((const float4*)x, (const float4*)W2, N, 128);  // 9
    k_aggr<<<gWarp, 256>>>(b2, N, 1);                                  // 10

    // layer 3 + pool (block pre-reduction to kill atomic contention)
    k_gemm<0><<<gGemm, 256>>>((const float4*)x, (const float4*)W3, N, 128);  // 11
    k_aggr_pool<<<gWarp, 256>>>(b3, batch, N);                         // 12

    // head
    k_final<<<1, 128>>>(Wc, bc, out);                                  // 13
}

// round 16
// speedup vs baseline: 1.9825x; 1.0513x over previous
#include <cuda_runtime.h>
#include <cuda_fp16.h>
#include <cstdint>

#define NMAX 100000
#define EMAX 1600000
#define NG   64
// hidden dim = 128: fp16 row = 32 uint2 (4 halves/lane), fp32 row = 32 float4

typedef unsigned long long ull_t;

// ---------------- scratch (static device globals; no allocation) ----------
__device__ uint2  g_bufH[(size_t)NMAX * 32];   // GEMM output (h*dinv) in fp16
__device__ float4 g_bufB[(size_t)NMAX * 32];   // aggregation output (fp32)
__device__ int    g_deg[NMAX];
__device__ int    g_rowptr[NMAX + 1];
__device__ int    g_pos[NMAX];
__device__ int    g_csr[EMAX];
__device__ float  g_pooled[NG * 128];
__device__ float  g_cnt[NG];
__device__ int    g_bsum[128];
__device__ int    g_is64;   // 1 if index tensors are int64, 0 if int32

// ---------------- packed f32x2 helpers (sm_103a FFMA2) ---------------------
__device__ __forceinline__ ull_t pack2(float v) {
    ull_t r;
    unsigned u = __float_as_uint(v);
    asm("mov.b64 %0, {%1, %1};" : "=l"(r) : "r"(u));
    return r;
}
__device__ __forceinline__ void ffma2(ull_t& d, ull_t a, ull_t b) {
    asm("fma.rn.f32x2 %0, %1, %2, %0;" : "+l"(d) : "l"(a), "l"(b));
}
__device__ __forceinline__ void unpack2(ull_t v, float& lo, float& hi) {
    unsigned a, b;
    asm("mov.b64 {%0, %1}, %2;" : "=r"(a), "=r"(b) : "l"(v));
    lo = __uint_as_float(a);
    hi = __uint_as_float(b);
}

__device__ __forceinline__ int idx_src(const int* ei, int E, int i, int is64) {
    return is64 ? ei[2 * i] : ei[i];
}
__device__ __forceinline__ int idx_dst(const int* ei, int E, int i, int is64) {
    return is64 ? ei[2 * (E + i)] : ei[E + i];
}
__device__ __forceinline__ int idx_at(const int* p, int i, int is64) {
    return is64 ? p[2 * i] : p[i];
}
__device__ __forceinline__ float dinv_of(int node) {
    return rsqrtf((float)(g_deg[node] + 1));
}

// fp16 pack/unpack
__device__ __forceinline__ uint2 pack_h4(float a, float b, float c, float d) {
    __half2 h0 = __floats2half2_rn(a, b);
    __half2 h1 = __floats2half2_rn(c, d);
    uint2 u;
    u.x = *reinterpret_cast<unsigned*>(&h0);
    u.y = *reinterpret_cast<unsigned*>(&h1);
    return u;
}
__device__ __forceinline__ void unpack_h4(uint2 u, float4& f) {
    __half2 h0 = *reinterpret_cast<__half2*>(&u.x);
    __half2 h1 = *reinterpret_cast<__half2*>(&u.y);
    float2 a = __half22float2(h0);
    float2 b = __half22float2(h1);
    f.x = a.x; f.y = a.y; f.z = b.x; f.w = b.y;
}

// ---------------- setup0: zero deg/pooled/cnt + dtype detect ---------------
__global__ void k_setup0(const int* __restrict__ ei, int N) {
    int i = blockIdx.x * blockDim.x + threadIdx.x;
    if (i < N) g_deg[i] = 0;
    if (i < NG * 128) g_pooled[i] = 0.f;
    if (i < NG) g_cnt[i] = 0.f;
    if (blockIdx.x == 0 && threadIdx.x < 32) {
        int lane = threadIdx.x, nz = 0;
        #pragma unroll
        for (int k = lane; k < 128; k += 32)
            nz |= (ei[2 * k + 1] != 0);
        unsigned m = __ballot_sync(0xffffffffu, nz != 0);
        if (lane == 0) g_is64 = (m == 0u) ? 1 : 0;
    }
}

// ---------------- degree histogram over dst --------------------------------
__global__ void k_deg(const int* __restrict__ ei, int E) {
    int i = blockIdx.x * blockDim.x + threadIdx.x;
    int is64 = g_is64;
    if (i < E) atomicAdd(&g_deg[idx_dst(ei, E, i, is64)], 1);
}

// ---------------- block-wise inclusive scan of deg -> rowptr[i+1] ---------
__global__ void k_scan1(int N) {
    __shared__ int sh[1024];
    int i = blockIdx.x * 1024 + threadIdx.x;
    int v = (i < N) ? g_deg[i] : 0;
    sh[threadIdx.x] = v;
    __syncthreads();
    #pragma unroll
    for (int off = 1; off < 1024; off <<= 1) {
        int t = (threadIdx.x >= off) ? sh[threadIdx.x - off] : 0;
        __syncthreads();
        sh[threadIdx.x] += t;
        __syncthreads();
    }
    if (i < N) g_rowptr[i + 1] = sh[threadIdx.x];
    if (threadIdx.x == 1023) g_bsum[blockIdx.x] = sh[1023];
}

// parallel exclusive scan of up to 128 block sums
__global__ void k_scan2(int nb) {
    __shared__ int sh[128];
    int t = threadIdx.x;
    int v = (t < nb) ? g_bsum[t] : 0;
    sh[t] = v;
    __syncthreads();
    #pragma unroll
    for (int off = 1; off < 128; off <<= 1) {
        int u = (t >= off) ? sh[t - off] : 0;
        __syncthreads();
        sh[t] += u;
        __syncthreads();
    }
    if (t < nb) g_bsum[t] = sh[t] - v;   // exclusive prefix
}

// finalize rowptr, init pos cursor, count nodes per graph
__global__ void k_scan3(const int* __restrict__ batch, int N) {
    int i = blockIdx.x * 1024 + threadIdx.x;
    if (i < N) {
        int v = g_rowptr[i + 1] + g_bsum[blockIdx.x];
        g_rowptr[i + 1] = v;
        if (i + 1 < N) g_pos[i + 1] = v;
        atomicAdd(&g_cnt[idx_at(batch, i, g_is64)], 1.0f);
    }
    if (i == 0) { g_rowptr[0] = 0; g_pos[0] = 0; }
}

// ---------------- CSR build: csr[slot(dst)] = src --------------------------
__global__ void k_build(const int* __restrict__ ei, int E) {
    int i = blockIdx.x * blockDim.x + threadIdx.x;
    int is64 = g_is64;
    if (i < E) {
        int d = idx_dst(ei, E, i, is64);
        int p = atomicAdd(&g_pos[d], 1);
        g_csr[p] = idx_src(ei, E, i, is64);
    }
}

// ---------------- GEMM: g_bufH = fp16((IN[N,K] @ W[K,128]) * dinv[row]) ----
// 64x128 tile, 256 threads, K-tile 32, FFMA2 row-pairs (round-9 proven best).
#define XS_STRIDE 66
template <int USE_EXT>
__global__ __launch_bounds__(256) void k_gemm(
    const float4* __restrict__ Xext,
    const float4* __restrict__ W4, int N, int K)
{
    __shared__ float  xs_t[32 * XS_STRIDE];   // transposed X tile [kk][row]
    __shared__ float4 ws4[32 * 32];           // W tile [kk][col4]
    const float4* X = USE_EXT ? Xext : g_bufB;
    const int K4 = K >> 2;

    int tid = threadIdx.x;
    int row0 = blockIdx.x * 64;
    int tx = tid & 31;   // col group: cols [tx*4, tx*4+3]
    int ty = tid >> 5;   // row group: rows [ty*8, ty*8+7] = 4 row-pairs

    ull_t acc[4][4];
    #pragma unroll
    for (int rp = 0; rp < 4; rp++)
        #pragma unroll
        for (int c = 0; c < 4; c++) acc[rp][c] = 0ull;

    for (int k0 = 0; k0 < K; k0 += 32) {
        int k0q = k0 >> 2;
        // load X tile: 64 rows x 8 float4, store transposed [kk][row]
        #pragma unroll
        for (int t = 0; t < 2; t++) {
            int f4 = tid + t * 256;
            int row = f4 >> 3;
            int kk4 = f4 & 7;
            float4 v = make_float4(0.f, 0.f, 0.f, 0.f);
            int gr = row0 + row;
            if (gr < N)
                v = X[(size_t)gr * K4 + k0q + kk4];
            xs_t[(kk4 * 4 + 0) * XS_STRIDE + row] = v.x;
            xs_t[(kk4 * 4 + 1) * XS_STRIDE + row] = v.y;
            xs_t[(kk4 * 4 + 2) * XS_STRIDE + row] = v.z;
            xs_t[(kk4 * 4 + 3) * XS_STRIDE + row] = v.w;
        }
        // load W tile: 32 k-rows x 32 float4
        {
            int kk = tid >> 5;
            int c4 = tid & 31;
            #pragma unroll
            for (int rep = 0; rep < 4; rep++) {
                int kkk = kk + rep * 8;
                ws4[kkk * 32 + c4] = W4[(size_t)(k0 + kkk) * 32 + c4];
            }
        }
        __syncthreads();
        #pragma unroll
        for (int kk = 0; kk < 32; kk++) {
            float4 b = ws4[kk * 32 + tx];
            ull_t bx = pack2(b.x);
            ull_t by = pack2(b.y);
            ull_t bz = pack2(b.z);
            ull_t bw = pack2(b.w);
            const float* ar = xs_t + kk * XS_STRIDE + ty * 8;
            #pragma unroll
            for (int rp = 0; rp < 4; rp++) {
                ull_t a2 = *reinterpret_cast<const ull_t*>(ar + rp * 2);
                ffma2(acc[rp][0], a2, bx);
                ffma2(acc[rp][1], a2, by);
                ffma2(acc[rp][2], a2, bz);
                ffma2(acc[rp][3], a2, bw);
            }
        }
        __syncthreads();
    }
    #pragma unroll
    for (int rp = 0; rp < 4; rp++) {
        int re = row0 + ty * 8 + rp * 2;   // even row
        if (re < N) {
            float x0, x1, y0, y1, z0, z1, w0, w1;
            unpack2(acc[rp][0], x0, x1);
            unpack2(acc[rp][1], y0, y1);
            unpack2(acc[rp][2], z0, z1);
            unpack2(acc[rp][3], w0, w1);
            float d0 = dinv_of(re);
            g_bufH[(size_t)re * 32 + tx] =
                pack_h4(x0 * d0, y0 * d0, z0 * d0, w0 * d0);
            if (re + 1 < N) {
                float d1 = dinv_of(re + 1);
                g_bufH[(size_t)(re + 1) * 32 + tx] =
                    pack_h4(x1 * d1, y1 * d1, z1 * d1, w1 * d1);
            }
        }
    }
}

// ---------------- fp16 gather: full 128-feature row, 1 LDG.64/lane/edge ----
__device__ __forceinline__ float4 gather_sum_h(int w, int lane) {
    float4 acc;
    unpack_h4(g_bufH[(size_t)w * 32 + lane], acc);   // self loop
    int beg = g_rowptr[w], end = g_rowptr[w + 1];
    int j = beg;
    for (; j + 3 < end; j += 4) {
        int s0 = g_csr[j + 0];
        int s1 = g_csr[j + 1];
        int s2 = g_csr[j + 2];
        int s3 = g_csr[j + 3];
        uint2 u0 = g_bufH[(size_t)s0 * 32 + lane];
        uint2 u1 = g_bufH[(size_t)s1 * 32 + lane];
        uint2 u2 = g_bufH[(size_t)s2 * 32 + lane];
        uint2 u3 = g_bufH[(size_t)s3 * 32 + lane];
        float4 v0, v1, v2, v3;
        unpack_h4(u0, v0); unpack_h4(u1, v1);
        unpack_h4(u2, v2); unpack_h4(u3, v3);
        acc.x += (v0.x + v1.x) + (v2.x + v3.x);
        acc.y += (v0.y + v1.y) + (v2.y + v3.y);
        acc.z += (v0.z + v1.z) + (v2.z + v3.z);
        acc.w += (v0.w + v1.w) + (v2.w + v3.w);
    }
    for (; j < end; j++) {
        int s = g_csr[j];
        float4 v;
        unpack_h4(g_bufH[(size_t)s * 32 + lane], v);
        acc.x += v.x; acc.y += v.y; acc.z += v.z; acc.w += v.w;
    }
    return acc;
}

// ---------------- aggregation: warp per node, bufH -> bufB (fp32) ----------
__global__ __launch_bounds__(256) void k_aggr(
    const float* __restrict__ bias, int N, int relu)
{
    int w = (blockIdx.x * blockDim.x + threadIdx.x) >> 5;
    int lane = threadIdx.x & 31;
    if (w >= N) return;
    float4 acc = gather_sum_h(w, lane);
    float di = dinv_of(w);
    float bx = bias[lane * 4 + 0];
    float by = bias[lane * 4 + 1];
    float bz = bias[lane * 4 + 2];
    float bw = bias[lane * 4 + 3];
    float4 o;
    o.x = acc.x * di + bx;
    o.y = acc.y * di + by;
    o.z = acc.z * di + bz;
    o.w = acc.w * di + bw;
    if (relu) {
        o.x = fmaxf(o.x, 0.f); o.y = fmaxf(o.y, 0.f);
        o.z = fmaxf(o.z, 0.f); o.w = fmaxf(o.w, 0.f);
    }
    g_bufB[(size_t)w * 32 + lane] = o;
}

// ---------------- layer-3 aggregation + pooling, 32-warp pre-reduction -----
// batch is sorted: a 32-node block almost always maps to one graph. Tree-
// reduce 32 node vectors in shared (all 1024 threads), then 128 parallel
// atomics per block -> 32x fewer global atomics on the tiny g_pooled array.
__global__ __launch_bounds__(1024) void k_aggr_pool(
    const float* __restrict__ bias,
    const int* __restrict__ batch, int N)
{
    __shared__ float sacc[32 * 128];
    __shared__ int   sg[32];
    __shared__ int   s_uniform;
    int wid = threadIdx.x >> 5;
    int lane = threadIdx.x & 31;
    int w = blockIdx.x * 32 + wid;
    bool valid = (w < N);

    float4 o = make_float4(0.f, 0.f, 0.f, 0.f);
    int g = -1;
    if (valid) {
        float4 acc = gather_sum_h(w, lane);
        float di = dinv_of(w);
        o.x = acc.x * di + bias[lane * 4 + 0];
        o.y = acc.y * di + bias[lane * 4 + 1];
        o.z = acc.z * di + bias[lane * 4 + 2];
        o.w = acc.w * di + bias[lane * 4 + 3];
        g = idx_at(batch, w, g_is64);
    }
    if (lane == 0) sg[wid] = g;
    float* row = sacc + wid * 128 + lane * 4;
    row[0] = o.x; row[1] = o.y; row[2] = o.z; row[3] = o.w;
    if (threadIdx.x == 0) s_uniform = 1;
    __syncthreads();

    // uniformity check (first warp scans the 32 graph ids)
    if (wid == 0) {
        int g0 = sg[0];
        int gi = sg[lane];
        unsigned bad = __ballot_sync(0xffffffffu, gi >= 0 && gi != g0);
        if (lane == 0 && (bad != 0u || g0 < 0)) s_uniform = 0;
    }
    __syncthreads();

    if (s_uniform) {
        // tree reduction over 32 rows: thread = (row-slot tid>>7, feature tid&127)
        int f = threadIdx.x & 127;
        int rs = threadIdx.x >> 7;   // 0..7
        #pragma unroll
        for (int s = 16; s >= 1; s >>= 1) {
            for (int r = rs; r < s; r += 8)
                sacc[r * 128 + f] += sacc[(r + s) * 128 + f];
            __syncthreads();
        }
        if (threadIdx.x < 128)
            atomicAdd(&g_pooled[sg[0] * 128 + threadIdx.x], sacc[threadIdx.x]);
    } else if (valid) {
        float* p = g_pooled + g * 128 + lane * 4;
        atomicAdd(p + 0, o.x);
        atomicAdd(p + 1, o.y);
        atomicAdd(p + 2, o.z);
        atomicAdd(p + 3, o.w);
    }
}

// ---------------- head: out[g,c] = (pooled[g]/cnt[g]) @ Wc + bc -----------
__global__ void k_final(const float* __restrict__ Wc,
                        const float* __restrict__ bc,
                        float* __restrict__ out)
{
    int t = threadIdx.x;   // 128 threads: (g, c)
    if (t >= NG * 2) return;
    int g = t >> 1;
    int c = t & 1;
    float s = 0.f;
    const float* p = g_pooled + g * 128;
    #pragma unroll 8
    for (int f = 0; f < 128; f++) s += p[f] * Wc[f * 2 + c];
    float inv = 1.f / fmaxf(g_cnt[g], 1.0f);
    out[t] = s * inv + bc[c];
}

// ---------------- launch ----------------------------------------------------
extern "C" void kernel_launch(void* const* d_in, const int* in_sizes, int n_in,
                              void* d_out, int out_size) {
    const float* x     = (const float*)d_in[0];
    const int*   ei    = (const int*)d_in[1];     // int32 (or int64, auto-detected)
    const int*   batch = (const int*)d_in[2];
    const float* W1 = (const float*)d_in[3];
    const float* b1 = (const float*)d_in[4];
    const float* W2 = (const float*)d_in[5];
    const float* b2 = (const float*)d_in[6];
    const float* W3 = (const float*)d_in[7];
    const float* b3 = (const float*)d_in[8];
    const float* Wc = (const float*)d_in[9];
    const float* bc = (const float*)d_in[10];
    float* out = (float*)d_out;

    const int Fin = 256;
    int N = in_sizes[0] / Fin;
    int E = in_sizes[1] / 2;

    int nb1024 = (N + 1023) / 1024;
    int gN256  = (N + 255) / 256;
    int gE256  = (E + 255) / 256;
    int gWarp  = (int)(((long long)N * 32 + 255) / 256);
    int gPool  = (N + 31) / 32;
    int gGemm  = (N + 63) / 64;

    // launches 1-3
    k_setup0<<<gN256, 256>>>(ei, N);                                   // 1
    k_deg<<<gE256, 256>>>(ei, E);                                      // 2
    k_scan1<<<nb1024, 1024>>>(N);                                      // 3

    // launch 4: layer-1 GEMM (profiled by ncu) — needs only g_deg
    k_gemm<1><<<gGemm, 256>>>((const float4*)x, (const float4*)W1, N, 256);  // 4

    // finish CSR
    k_scan2<<<1, 128>>>(nb1024);                                       // 5
    k_scan3<<<nb1024, 1024>>>(batch, N);                               // 6
    k_build<<<gE256, 256>>>(ei, E);                                    // 7

    // layer 1 aggregate -> bufB
    k_aggr<<<gWarp, 256>>>(b1, N, 1);                                  // 8

    // layer 2
    k_gemm<0><<<gGemm, 256>>>((const float4*)x, (const float4*)W2, N, 128);  // 9
    k_aggr<<<gWarp, 256>>>(b2, N, 1);                                  // 10

    // layer 3 + pool (32-warp pre-reduction to kill atomic contention)
    k_gemm<0><<<gGemm, 256>>>((const float4*)x, (const float4*)W3, N, 128);  // 11
    k_aggr_pool<<<gPool, 1024>>>(b3, batch, N);                        // 12

    // head
    k_final<<<1, 128>>>(Wc, bc, out);                                  // 13
}

// round 17
// speedup vs baseline: 2.2610x; 1.1405x over previous
#include <cuda_runtime.h>
#include <cuda_fp16.h>
#include <cstdint>

#define NMAX 100000
#define EMAX 1600000
#define NG   64
#define NBPOOL ((NMAX + 31) / 32)
// hidden dim = 128: fp16 row = 32 uint2 (4 halves/lane), fp32 row = 32 float4

typedef unsigned long long ull_t;

// ---------------- scratch (static device globals; no allocation) ----------
__device__ uint2  g_bufH[(size_t)NMAX * 32];   // GEMM output (h*dinv) in fp16
__device__ float4 g_bufB[(size_t)NMAX * 32];   // aggregation output (fp32)
__device__ int    g_deg[NMAX];
__device__ int    g_rowptr[NMAX + 1];
__device__ int    g_pos[NMAX];
__device__ int    g_csr[EMAX];
__device__ float  g_partial[(size_t)NBPOOL * 128]; // per-block pooled partials
__device__ int    g_gid[NBPOOL];                   // graph id per pool block
__device__ float  g_pooled[NG * 128];              // boundary-row tail (atomics)
__device__ int    g_bsum[128];
__device__ int    g_is64;   // 1 if index tensors are int64, 0 if int32

// ---------------- packed f32x2 helpers (sm_103a FFMA2) ---------------------
__device__ __forceinline__ ull_t pack2(float v) {
    ull_t r;
    unsigned u = __float_as_uint(v);
    asm("mov.b64 %0, {%1, %1};" : "=l"(r) : "r"(u));
    return r;
}
__device__ __forceinline__ void ffma2(ull_t& d, ull_t a, ull_t b) {
    asm("fma.rn.f32x2 %0, %1, %2, %0;" : "+l"(d) : "l"(a), "l"(b));
}
__device__ __forceinline__ void unpack2(ull_t v, float& lo, float& hi) {
    unsigned a, b;
    asm("mov.b64 {%0, %1}, %2;" : "=r"(a), "=r"(b) : "l"(v));
    lo = __uint_as_float(a);
    hi = __uint_as_float(b);
}

__device__ __forceinline__ int idx_src(const int* ei, int E, int i, int is64) {
    return is64 ? ei[2 * i] : ei[i];
}
__device__ __forceinline__ int idx_dst(const int* ei, int E, int i, int is64) {
    return is64 ? ei[2 * (E + i)] : ei[E + i];
}
__device__ __forceinline__ int idx_at(const int* p, int i, int is64) {
    return is64 ? p[2 * i] : p[i];
}
__device__ __forceinline__ float dinv_of(int node) {
    return rsqrtf((float)(g_deg[node] + 1));
}

// fp16 pack/unpack
__device__ __forceinline__ uint2 pack_h4(float a, float b, float c, float d) {
    __half2 h0 = __floats2half2_rn(a, b);
    __half2 h1 = __floats2half2_rn(c, d);
    uint2 u;
    u.x = *reinterpret_cast<unsigned*>(&h0);
    u.y = *reinterpret_cast<unsigned*>(&h1);
    return u;
}
__device__ __forceinline__ void unpack_h4(uint2 u, float4& f) {
    __half2 h0 = *reinterpret_cast<__half2*>(&u.x);
    __half2 h1 = *reinterpret_cast<__half2*>(&u.y);
    float2 a = __half22float2(h0);
    float2 b = __half22float2(h1);
    f.x = a.x; f.y = a.y; f.z = b.x; f.w = b.y;
}

// ---------------- setup0: zero deg/pooled + dtype detect -------------------
__global__ void k_setup0(const int* __restrict__ ei, int N) {
    int i = blockIdx.x * blockDim.x + threadIdx.x;
    if (i < N) g_deg[i] = 0;
    if (i < NG * 128) g_pooled[i] = 0.f;
    if (blockIdx.x == 0 && threadIdx.x < 32) {
        int lane = threadIdx.x, nz = 0;
        #pragma unroll
        for (int k = lane; k < 128; k += 32)
            nz |= (ei[2 * k + 1] != 0);
        unsigned m = __ballot_sync(0xffffffffu, nz != 0);
        if (lane == 0) g_is64 = (m == 0u) ? 1 : 0;
    }
}

// ---------------- degree histogram over dst --------------------------------
__global__ void k_deg(const int* __restrict__ ei, int E) {
    int i = blockIdx.x * blockDim.x + threadIdx.x;
    int is64 = g_is64;
    if (i < E) atomicAdd(&g_deg[idx_dst(ei, E, i, is64)], 1);
}

// ---------------- block-wise inclusive scan of deg -> rowptr[i+1] ---------
__global__ void k_scan1(int N) {
    __shared__ int sh[1024];
    int i = blockIdx.x * 1024 + threadIdx.x;
    int v = (i < N) ? g_deg[i] : 0;
    sh[threadIdx.x] = v;
    __syncthreads();
    #pragma unroll
    for (int off = 1; off < 1024; off <<= 1) {
        int t = (threadIdx.x >= off) ? sh[threadIdx.x - off] : 0;
        __syncthreads();
        sh[threadIdx.x] += t;
        __syncthreads();
    }
    if (i < N) g_rowptr[i + 1] = sh[threadIdx.x];
    if (threadIdx.x == 1023) g_bsum[blockIdx.x] = sh[1023];
}

// finalize rowptr (block computes its bsum prefix in-place) + init pos
__global__ void k_scan3(int N) {
    __shared__ int sP;
    if (threadIdx.x < 32) {
        int s = 0;
        for (int t = threadIdx.x; t < blockIdx.x; t += 32) s += g_bsum[t];
        #pragma unroll
        for (int off = 16; off; off >>= 1)
            s += __shfl_down_sync(0xffffffffu, s, off);
        if (threadIdx.x == 0) sP = s;
    }
    __syncthreads();
    int P = sP;
    int i = blockIdx.x * 1024 + threadIdx.x;
    if (i < N) {
        int v = g_rowptr[i + 1] + P;
        g_rowptr[i + 1] = v;
        if (i + 1 < N) g_pos[i + 1] = v;
    }
    if (i == 0) { g_rowptr[0] = 0; g_pos[0] = 0; }
}

// ---------------- CSR build: csr[slot(dst)] = src --------------------------
__global__ void k_build(const int* __restrict__ ei, int E) {
    int i = blockIdx.x * blockDim.x + threadIdx.x;
    int is64 = g_is64;
    if (i < E) {
        int d = idx_dst(ei, E, i, is64);
        int p = atomicAdd(&g_pos[d], 1);
        g_csr[p] = idx_src(ei, E, i, is64);
    }
}

// ---------------- GEMM: g_bufH = fp16((IN[N,K] @ W[K,128]) * dinv[row]) ----
// 64x128 tile, 256 threads, K-tile 32, FFMA2 row-pairs (LDS-crossbar bound).
#define XS_STRIDE 66
template <int USE_EXT>
__global__ __launch_bounds__(256) void k_gemm(
    const float4* __restrict__ Xext,
    const float4* __restrict__ W4, int N, int K)
{
    __shared__ float  xs_t[32 * XS_STRIDE];   // transposed X tile [kk][row]
    __shared__ float4 ws4[32 * 32];           // W tile [kk][col4]
    const float4* X = USE_EXT ? Xext : g_bufB;
    const int K4 = K >> 2;

    int tid = threadIdx.x;
    int row0 = blockIdx.x * 64;
    int tx = tid & 31;   // col group: cols [tx*4, tx*4+3]
    int ty = tid >> 5;   // row group: rows [ty*8, ty*8+7] = 4 row-pairs

    ull_t acc[4][4];
    #pragma unroll
    for (int rp = 0; rp < 4; rp++)
        #pragma unroll
        for (int c = 0; c < 4; c++) acc[rp][c] = 0ull;

    for (int k0 = 0; k0 < K; k0 += 32) {
        int k0q = k0 >> 2;
        #pragma unroll
        for (int t = 0; t < 2; t++) {
            int f4 = tid + t * 256;
            int row = f4 >> 3;
            int kk4 = f4 & 7;
            float4 v = make_float4(0.f, 0.f, 0.f, 0.f);
            int gr = row0 + row;
            if (gr < N)
                v = X[(size_t)gr * K4 + k0q + kk4];
            xs_t[(kk4 * 4 + 0) * XS_STRIDE + row] = v.x;
            xs_t[(kk4 * 4 + 1) * XS_STRIDE + row] = v.y;
            xs_t[(kk4 * 4 + 2) * XS_STRIDE + row] = v.z;
            xs_t[(kk4 * 4 + 3) * XS_STRIDE + row] = v.w;
        }
        {
            int kk = tid >> 5;
            int c4 = tid & 31;
            #pragma unroll
            for (int rep = 0; rep < 4; rep++) {
                int kkk = kk + rep * 8;
                ws4[kkk * 32 + c4] = W4[(size_t)(k0 + kkk) * 32 + c4];
            }
        }
        __syncthreads();
        #pragma unroll
        for (int kk = 0; kk < 32; kk++) {
            float4 b = ws4[kk * 32 + tx];
            ull_t bx = pack2(b.x);
            ull_t by = pack2(b.y);
            ull_t bz = pack2(b.z);
            ull_t bw = pack2(b.w);
            const float* ar = xs_t + kk * XS_STRIDE + ty * 8;
            #pragma unroll
            for (int rp = 0; rp < 4; rp++) {
                ull_t a2 = *reinterpret_cast<const ull_t*>(ar + rp * 2);
                ffma2(acc[rp][0], a2, bx);
                ffma2(acc[rp][1], a2, by);
                ffma2(acc[rp][2], a2, bz);
                ffma2(acc[rp][3], a2, bw);
            }
        }
        __syncthreads();
    }
    #pragma unroll
    for (int rp = 0; rp < 4; rp++) {
        int re = row0 + ty * 8 + rp * 2;   // even row
        if (re < N) {
            float x0, x1, y0, y1, z0, z1, w0, w1;
            unpack2(acc[rp][0], x0, x1);
            unpack2(acc[rp][1], y0, y1);
            unpack2(acc[rp][2], z0, z1);
            unpack2(acc[rp][3], w0, w1);
            float d0 = dinv_of(re);
            g_bufH[(size_t)re * 32 + tx] =
                pack_h4(x0 * d0, y0 * d0, z0 * d0, w0 * d0);
            if (re + 1 < N) {
                float d1 = dinv_of(re + 1);
                g_bufH[(size_t)(re + 1) * 32 + tx] =
                    pack_h4(x1 * d1, y1 * d1, z1 * d1, w1 * d1);
            }
        }
    }
}

// ---------------- fp16 gather: full 128-feature row, 1 LDG.64/lane/edge ----
__device__ __forceinline__ float4 gather_sum_h(int w, int lane) {
    float4 acc;
    unpack_h4(g_bufH[(size_t)w * 32 + lane], acc);   // self loop
    int beg = g_rowptr[w], end = g_rowptr[w + 1];
    int j = beg;
    for (; j + 3 < end; j += 4) {
        int s0 = g_csr[j + 0];
        int s1 = g_csr[j + 1];
        int s2 = g_csr[j + 2];
        int s3 = g_csr[j + 3];
        uint2 u0 = g_bufH[(size_t)s0 * 32 + lane];
        uint2 u1 = g_bufH[(size_t)s1 * 32 + lane];
        uint2 u2 = g_bufH[(size_t)s2 * 32 + lane];
        uint2 u3 = g_bufH[(size_t)s3 * 32 + lane];
        float4 v0, v1, v2, v3;
        unpack_h4(u0, v0); unpack_h4(u1, v1);
        unpack_h4(u2, v2); unpack_h4(u3, v3);
        acc.x += (v0.x + v1.x) + (v2.x + v3.x);
        acc.y += (v0.y + v1.y) + (v2.y + v3.y);
        acc.z += (v0.z + v1.z) + (v2.z + v3.z);
        acc.w += (v0.w + v1.w) + (v2.w + v3.w);
    }
    for (; j < end; j++) {
        int s = g_csr[j];
        float4 v;
        unpack_h4(g_bufH[(size_t)s * 32 + lane], v);
        acc.x += v.x; acc.y += v.y; acc.z += v.z; acc.w += v.w;
    }
    return acc;
}

// ---------------- aggregation: warp per node, bufH -> bufB (fp32) ----------
__global__ __launch_bounds__(256) void k_aggr(
    const float* __restrict__ bias, int N, int relu)
{
    int w = (blockIdx.x * blockDim.x + threadIdx.x) >> 5;
    int lane = threadIdx.x & 31;
    if (w >= N) return;
    float4 acc = gather_sum_h(w, lane);
    float di = dinv_of(w);
    float bx = bias[lane * 4 + 0];
    float by = bias[lane * 4 + 1];
    float bz = bias[lane * 4 + 2];
    float bw = bias[lane * 4 + 3];
    float4 o;
    o.x = acc.x * di + bx;
    o.y = acc.y * di + by;
    o.z = acc.z * di + bz;
    o.w = acc.w * di + bw;
    if (relu) {
        o.x = fmaxf(o.x, 0.f); o.y = fmaxf(o.y, 0.f);
        o.z = fmaxf(o.z, 0.f); o.w = fmaxf(o.w, 0.f);
    }
    g_bufB[(size_t)w * 32 + lane] = o;
}

// ---------------- layer-3 aggregation + pooling: atomic-free partials ------
// 32 warps/block. Rows matching the block's lead graph id reduce in shared
// and store ONE partial vector (plain STG). Rare boundary rows (batch is
// sorted; <=63 straddling blocks) fall back to atomics on g_pooled.
__global__ __launch_bounds__(1024) void k_aggr_pool(
    const float* __restrict__ bias,
    const int* __restrict__ batch, int N)
{
    __shared__ float sacc[32 * 128];
    __shared__ int   sg[32];
    int wid = threadIdx.x >> 5;
    int lane = threadIdx.x & 31;
    int w = blockIdx.x * 32 + wid;
    bool valid = (w < N);

    float4 o = make_float4(0.f, 0.f, 0.f, 0.f);
    int g = -1;
    if (valid) {
        float4 acc = gather_sum_h(w, lane);
        float di = dinv_of(w);
        o.x = acc.x * di + bias[lane * 4 + 0];
        o.y = acc.y * di + bias[lane * 4 + 1];
        o.z = acc.z * di + bias[lane * 4 + 2];
        o.w = acc.w * di + bias[lane * 4 + 3];
        g = idx_at(batch, w, g_is64);
    }
    if (lane == 0) sg[wid] = g;
    float* row = sacc + wid * 128 + lane * 4;
    row[0] = o.x; row[1] = o.y; row[2] = o.z; row[3] = o.w;
    __syncthreads();

    int g0 = sg[0];   // lead graph (node w=blockIdx*32 always valid)
    // boundary rows: atomic into tail, then zero their shared row
    if (valid && g != g0) {
        float* p = g_pooled + g * 128 + lane * 4;
        atomicAdd(p + 0, o.x);
        atomicAdd(p + 1, o.y);
        atomicAdd(p + 2, o.z);
        atomicAdd(p + 3, o.w);
        row[0] = 0.f; row[1] = 0.f; row[2] = 0.f; row[3] = 0.f;
    }
    __syncthreads();

    // tree reduction over 32 rows: thread = (row-slot tid>>7, feature tid&127)
    int f = threadIdx.x & 127;
    int rs = threadIdx.x >> 7;   // 0..7
    #pragma unroll
    for (int s = 16; s >= 1; s >>= 1) {
        for (int r = rs; r < s; r += 8)
            sacc[r * 128 + f] += sacc[(r + s) * 128 + f];
        __syncthreads();
    }
    if (threadIdx.x < 128)
        g_partial[(size_t)blockIdx.x * 128 + threadIdx.x] = sacc[threadIdx.x];
    if (threadIdx.x == 0)
        g_gid[blockIdx.x] = g0;
}

// ---------------- head: block per graph -------------------------------------
// Sums this graph's partial vectors (gid is sorted: binary search the block
// range), adds the atomic tail, counts nodes by binary search on sorted
// batch, then computes out[g, 0:2] = (pooled/cnt) @ Wc + bc.
__global__ __launch_bounds__(128) void k_final(
    const int* __restrict__ batch, int N, int nb,
    const float* __restrict__ Wc,
    const float* __restrict__ bc,
    float* __restrict__ out)
{
    __shared__ int   sb[4];      // blk_lo, blk_hi, node_lo, node_hi
    __shared__ float sr[256];
    int g = blockIdx.x;
    int f = threadIdx.x;
    int is64 = g_is64;

    if (f < 4) {
        int target = (f & 1) ? g + 1 : g;   // lower bound of target
        int lo = 0, hi = (f < 2) ? nb : N;
        if (f < 2) {
            while (lo < hi) {
                int mid = (lo + hi) >> 1;
                if (g_gid[mid] < target) lo = mid + 1; else hi = mid;
            }
        } else {
            while (lo < hi) {
                int mid = (lo + hi) >> 1;
                if (idx_at(batch, mid, is64) < target) lo = mid + 1; else hi = mid;
            }
        }
        sb[f] = lo;
    }
    __syncthreads();
    int blo = sb[0], bhi = sb[1];
    float cnt = (float)(sb[3] - sb[2]);

    float s = g_pooled[g * 128 + f];   // boundary tail
    for (int b = blo; b < bhi; b++)
        s += g_partial[(size_t)b * 128 + f];

    float inv = 1.f / fmaxf(cnt, 1.0f);
    float pf = s * inv;
    sr[f]       = pf * Wc[f * 2 + 0];
    sr[128 + f] = pf * Wc[f * 2 + 1];
    __syncthreads();
    #pragma unroll
    for (int off = 64; off >= 1; off >>= 1) {
        if (f < off) {
            sr[f]       += sr[f + off];
            sr[128 + f] += sr[128 + f + off];
        }
        __syncthreads();
    }
    if (f < 2)
        out[g * 2 + f] = sr[f * 128] + bc[f];
}

// ---------------- launch ----------------------------------------------------
extern "C" void kernel_launch(void* const* d_in, const int* in_sizes, int n_in,
                              void* d_out, int out_size) {
    const float* x     = (const float*)d_in[0];
    const int*   ei    = (const int*)d_in[1];     // int32 (or int64, auto-detected)
    const int*   batch = (const int*)d_in[2];
    const float* W1 = (const float*)d_in[3];
    const float* b1 = (const float*)d_in[4];
    const float* W2 = (const float*)d_in[5];
    const float* b2 = (const float*)d_in[6];
    const float* W3 = (const float*)d_in[7];
    const float* b3 = (const float*)d_in[8];
    const float* Wc = (const float*)d_in[9];
    const float* bc = (const float*)d_in[10];
    float* out = (float*)d_out;

    const int Fin = 256;
    int N = in_sizes[0] / Fin;
    int E = in_sizes[1] / 2;

    int nb1024 = (N + 1023) / 1024;
    int gN256  = (N + 255) / 256;
    int gE256  = (E + 255) / 256;
    int gWarp  = (int)(((long long)N * 32 + 255) / 256);
    int gPool  = (N + 31) / 32;
    int gGemm  = (N + 63) / 64;

    // launches 1-3
    k_setup0<<<gN256, 256>>>(ei, N);                                   // 1
    k_deg<<<gE256, 256>>>(ei, E);                                      // 2
    k_scan1<<<nb1024, 1024>>>(N);                                      // 3

    // launch 4: layer-1 GEMM (profiled by ncu) — needs only g_deg
    k_gemm<1><<<gGemm, 256>>>((const float4*)x, (const float4*)W1, N, 256);  // 4

    // finish CSR
    k_scan3<<<nb1024, 1024>>>(N);                                      // 5
    k_build<<<gE256, 256>>>(ei, E);                                    // 6

    // layer 1 aggregate -> bufB
    k_aggr<<<gWarp, 256>>>(b1, N, 1);                                  // 7

    // layer 2
    k_gemm<0><<<gGemm, 256>>>((const float4*)x, (const float4*)W2, N, 128);  // 8
    k_aggr<<<gWarp, 256>>>(b2, N, 1);                                  // 9

    // layer 3 + pool (atomic-free partial pooling)
    k_gemm<0><<<gGemm, 256>>>((const float4*)x, (const float4*)W3, N, 128);  // 10
    k_aggr_pool<<<gPool, 1024>>>(b3, batch, N);                        // 11

    // head: block per graph
    k_final<<<NG, 128>>>(batch, N, gPool, Wc, bc, out);                // 12
}